// round 3
// baseline (speedup 1.0000x reference)
#include <cuda_runtime.h>
#include <cstdint>

// LSTM T=1024, B=64, D=512 — two-phase persistent kernel, 128 CTAs x 512 thr.
// Phase 1 (parallel): Zx[t] = x_t @ Wi + b for all t, CTA-local layout.
// Phase 2 (recurrent): z = Zx[t] + h @ Wh; gates; h update. Only the h-GEMM
// (half the FLOPs) sits on the sequential critical path.

#define TS   1024
#define BB   64
#define DD   512
#define NCTA 128
#define NTHR 512

#define BUF_STRIDE 516                  // floats/row (129 16B units, odd -> cf)
#define BUF_FLOATS (32 * BUF_STRIDE)    // 16512 floats = 66048 B
#define WS_FLOATS  (16 * 512)           // 8192 floats = 32768 B (one weight half)
#define RED_STRIDE 17
#define RED_FLOATS (8 * 64 * RED_STRIDE) // 8704 floats = 34816 B

// device scratch (static — no allocation)
__device__ float g_zx[(size_t)TS * NCTA * 1024];  // 512 MB: [t][cta][b][dloc][gate]
__device__ float g_hbuf[2][BB * DD];
__device__ unsigned g_count = 0;
__device__ volatile unsigned g_gen = 0;

__device__ __forceinline__ void fma2(unsigned long long& d,
                                     unsigned long long a,
                                     unsigned long long b) {
    asm volatile("fma.rn.f32x2 %0, %1, %2, %0;" : "+l"(d) : "l"(a), "l"(b));
}
__device__ __forceinline__ float sigf(float x) {
    return __fdividef(1.0f, 1.0f + __expf(-x));
}
__device__ __forceinline__ float tanhfast(float x) {
    float e = __expf(-2.0f * x);
    return __fdividef(1.0f - e, 1.0f + e);
}

__device__ __forceinline__ void cpa16(float* dst, const float* src) {
    unsigned s = (unsigned)__cvta_generic_to_shared(dst);
    asm volatile("cp.async.cg.shared.global [%0], [%1], 16;" :: "r"(s), "l"(src));
}
#define CPA_COMMIT() asm volatile("cp.async.commit_group;" ::: "memory")
#define CPA_WAIT1()  asm volatile("cp.async.wait_group 1;" ::: "memory")
#define CPA_WAIT0()  asm volatile("cp.async.wait_group 0;" ::: "memory")

// stage 32 rows x 512 floats (64 KB) global -> smem (row stride 516)
__device__ __forceinline__ void pf_tile(float* dst, const float* gsrc) {
    int r  = threadIdx.x >> 4;
    int c0 = threadIdx.x & 15;
    const float* s = gsrc + r * 512;
    float* d = dst + r * BUF_STRIDE;
#pragma unroll
    for (int j = 0; j < 8; ++j) {
        int c = c0 + j * 16;
        cpa16(d + c * 4, s + c * 4);
    }
}

// fill Ws (16 cols x 512 k) from W[k][2048] slice, XOR-swizzled 16B units
__device__ __forceinline__ void fill_ws(float* Ws, const float* W, int d0) {
    for (int i = threadIdx.x; i < 16 * 512; i += NTHR) {
        int c = i >> 9, k = i & 511;
        int zc = ((c >> 2) << 9) + d0 + (c & 3);
        float w = W[(size_t)k * 2048 + zc];
        int kq = k >> 2;
        int u  = (kq & ~7) | ((kq ^ (c >> 1)) & 7);
        Ws[(c << 7 | u) * 4 + (k & 3)] = w;
    }
}

// one 32-batch tile: 2 cols x 4 batches x 512 k, f32x2 FMA
__device__ __forceinline__ void gemm_tile(const float* __restrict__ Ws,
                                          const float* __restrict__ buf,
                                          unsigned long long* acc,
                                          int cp, int bhq, int chunk) {
    const ulonglong2* wp0 = (const ulonglong2*)Ws + (2 * cp) * 128 + chunk * 16;
    const ulonglong2* wp1 = wp0 + 128;
    const ulonglong2* ap  = (const ulonglong2*)buf + bhq * 129 + chunk * 16;
#pragma unroll 4
    for (int kk = 0; kk < 16; ++kk) {
        int u = (kk & 8) | ((kk ^ cp) & 7);
        ulonglong2 w0 = wp0[u];
        ulonglong2 w1 = wp1[u];
#pragma unroll
        for (int bi = 0; bi < 4; ++bi) {
            ulonglong2 a = ap[bi * 1032 + kk];
            fma2(acc[bi],     w0.x, a.x);
            fma2(acc[bi],     w0.y, a.y);
            fma2(acc[4 + bi], w1.x, a.x);
            fma2(acc[4 + bi], w1.y, a.y);
        }
    }
}

__device__ __forceinline__ void write_partials(float* red,
                                               unsigned long long* accA,
                                               unsigned long long* accB,
                                               int cp, int bhq, int chunk) {
#pragma unroll
    for (int h = 0; h < 2; ++h) {
        unsigned long long* ac = h ? accB : accA;
#pragma unroll
        for (int ci = 0; ci < 2; ++ci)
#pragma unroll
            for (int bi = 0; bi < 4; ++bi) {
                float2 p = *(float2*)&ac[ci * 4 + bi];
                int b = h * 32 + bhq + bi * 8;
                red[(chunk * 64 + b) * RED_STRIDE + 2 * cp + ci] = p.x + p.y;
            }
    }
}

__device__ __forceinline__ void bar_arrive() {
    __threadfence();
    __syncthreads();
    if (threadIdx.x == 0) {
        unsigned a = atomicAdd(&g_count, 1u);
        if (((a + 1u) & (NCTA - 1u)) == 0u) g_gen = g_gen + 1u;
    }
}
__device__ __forceinline__ void bar_wait(unsigned gen0, unsigned target) {
    if (threadIdx.x == 0) {
        while ((unsigned)(g_gen - gen0) < target) __nanosleep(32);
        __threadfence();
    }
    __syncthreads();
}

extern "C" __global__ void __launch_bounds__(NTHR, 1)
lstm_2phase(const float* __restrict__ x,    // [T,B,D]
            const float* __restrict__ c0,   // [B,D]
            const float* __restrict__ h0,   // [B,D]
            const float* __restrict__ Wi,   // [D,4D]
            const float* __restrict__ Wh,   // [D,4D]
            const float* __restrict__ bias, // [4D]
            float* __restrict__ out,
            long long out_size) {
    extern __shared__ float smem[];
    float* Ws   = smem;                       // 8192 floats
    float* buf0 = smem + WS_FLOATS;           // 16512
    float* buf1 = buf0 + BUF_FLOATS;          // 16512
    float* red  = buf1 + BUF_FLOATS;          // 8704

    const int tid = threadIdx.x;
    const int bid = blockIdx.x;
    const int d0  = bid * 4;

    const int cp    = tid & 7;
    const int chunk = (tid >> 5) & 7;
    const int bhq   = ((tid >> 3) & 3) | ((tid >> 8) << 2);

    const int eb  = tid >> 2;   // reducer roles (tid<256)
    const int edl = tid & 3;

    unsigned gen0 = 0;
    if (tid == 0) gen0 = g_gen;
    unsigned epoch = 0;

    // ===================== PHASE 1: Zx = x @ Wi + b =====================
    pf_tile(buf0, x);   // x_0 tile0
    CPA_COMMIT();
    fill_ws(Ws, Wi, d0);

    float b_i = 0.f, b_f = 0.f, b_g = 0.f, b_o = 0.f;
    if (tid < 256) {
        int d = d0 + edl;
        b_i = bias[d];
        b_f = bias[512 + d];
        b_g = bias[1024 + d];
        b_o = bias[1536 + d];
    }
    __syncthreads();

    float* zx_cta = g_zx + (size_t)bid * 1024;

    for (int t = 0; t < TS; ++t) {
        const float* xt = x + (size_t)t * 32768;

        unsigned long long accA[8], accB[8];
#pragma unroll
        for (int i = 0; i < 8; ++i) { accA[i] = 0ULL; accB[i] = 0ULL; }

        pf_tile(buf1, xt + 16384);           // tile1 of t
        CPA_COMMIT();
        CPA_WAIT1();                         // tile0 ready
        __syncthreads();
        gemm_tile(Ws, buf0, accA, cp, bhq, chunk);
        __syncthreads();                     // buf0 free

        int tn = (t < TS - 1) ? t + 1 : t;
        pf_tile(buf0, x + (size_t)tn * 32768);  // tile0 of t+1
        CPA_COMMIT();
        CPA_WAIT1();                         // tile1 ready
        __syncthreads();
        gemm_tile(Ws, buf1, accB, cp, bhq, chunk);

        write_partials(red, accA, accB, cp, bhq, chunk);
        __syncthreads();

        if (tid < 256) {
            float zi = b_i, zf = b_f, zg = b_g, zo = b_o;
#pragma unroll
            for (int ch = 0; ch < 8; ++ch) {
                const float* r = &red[(ch * 64 + eb) * RED_STRIDE + edl];
                zi += r[0];
                zf += r[4];
                zg += r[8];
                zo += r[12];
            }
            float4 v = make_float4(zi, zf, zg, zo);
            *(float4*)(zx_cta + (size_t)t * NCTA * 1024 + tid * 4) = v;
        }

        if ((t & 255) == 255) {              // bound CTA drift (keeps x in L2)
            bar_arrive();
            ++epoch;
            bar_wait(gen0, epoch);
        }
    }

    // ===================== PHASE 2: recurrence (h @ Wh) =====================
    CPA_WAIT0();
    __syncthreads();
    fill_ws(Ws, Wh, d0);

    float c_reg = 0.f;
    if (tid < 256) c_reg = c0[eb * DD + d0 + edl];
    __syncthreads();

    for (int t = 0; t < TS; ++t) {
        // prefetch this CTA's Zx[t] (independent of barrier)
        float4 zx = make_float4(0.f, 0.f, 0.f, 0.f);
        if (tid < 256)
            zx = *(const float4*)(zx_cta + (size_t)t * NCTA * 1024 + tid * 4);

        if (t > 0) bar_wait(gen0, epoch);    // h of step t-1 visible

        const float* hsrc = (t == 0) ? h0 : g_hbuf[t & 1];

        unsigned long long accA[8], accB[8];
#pragma unroll
        for (int i = 0; i < 8; ++i) { accA[i] = 0ULL; accB[i] = 0ULL; }

        pf_tile(buf0, hsrc);
        CPA_COMMIT();
        pf_tile(buf1, hsrc + 16384);
        CPA_COMMIT();

        CPA_WAIT1();
        __syncthreads();
        gemm_tile(Ws, buf0, accA, cp, bhq, chunk);

        CPA_WAIT0();
        __syncthreads();
        gemm_tile(Ws, buf1, accB, cp, bhq, chunk);

        write_partials(red, accA, accB, cp, bhq, chunk);
        __syncthreads();

        if (tid < 256) {
            float zi = zx.x, zf = zx.y, zg = zx.z, zo = zx.w;
#pragma unroll
            for (int ch = 0; ch < 8; ++ch) {
                const float* r = &red[(ch * 64 + eb) * RED_STRIDE + edl];
                zi += r[0];
                zf += r[4];
                zg += r[8];
                zo += r[12];
            }
            float cc = sigf(zf) * c_reg + sigf(zi) * tanhfast(zg);
            float hh = sigf(zo) * tanhfast(cc);
            c_reg = cc;
            int d = d0 + edl;
            __stcg(&g_hbuf[(t + 1) & 1][eb * DD + d], hh);
            out[(size_t)t * 32768 + eb * DD + d] = hh;
            if (t == TS - 1 && out_size >= 33554432LL + 65536LL) {
                out[33554432 + eb * DD + d] = cc;
                out[33554432 + 32768 + eb * DD + d] = hh;
            }
        }

        if (t < TS - 1) {
            bar_arrive();
            ++epoch;
        }
        __syncthreads();   // red reuse safety across iterations
    }
}

extern "C" void kernel_launch(void* const* d_in, const int* in_sizes, int n_in,
                              void* d_out, int out_size) {
    const float* x  = (const float*)d_in[0];
    const float* c0 = (const float*)d_in[1];
    const float* h0 = (const float*)d_in[2];
    const float* Wi = (const float*)d_in[3];
    const float* Wh = (const float*)d_in[4];
    const float* b  = (const float*)d_in[5];

    const int smem_bytes = (WS_FLOATS + 2 * BUF_FLOATS + RED_FLOATS) * 4; // 199680
    cudaFuncSetAttribute(lstm_2phase,
                         cudaFuncAttributeMaxDynamicSharedMemorySize,
                         smem_bytes);

    lstm_2phase<<<NCTA, NTHR, smem_bytes>>>(
        x, c0, h0, Wi, Wh, b, (float*)d_out, (long long)out_size);
}